// round 12
// baseline (speedup 1.0000x reference)
#include <cuda_runtime.h>
#include <cstdint>
#include <cstddef>

// Problem shape (fixed by the dataset)
#define S 8192
#define M 2048
#define E 64

#define KSPLIT 4
#define KSLICE (M / KSPLIT)      // 512
#define KC 32
#define TOKB 256                 // tokens per compute block
#define NCOMPUTE ((S / TOKB) * KSPLIT)   // 128
#define NZERO 148                // 1 block/SM; second slot left for branch B
#define NCHUNK (S / 32)          // 256 warp-sized token chunks

#define TILE4 4096               // float4s per zero tile (64 KB)

typedef unsigned long long u64;

// Scratch (device globals — no allocations allowed). Counters start zero
// (static init) and are reset in the zero kernel's tail each call, so every
// graph replay starts clean.
__device__ float    g_logits[(size_t)S * E];   // 2 MB split-K accumulator
__device__ float    g_colsum[E];
__device__ int      g_expert[S];
__device__ float    g_gate[S];
__device__ int      g_rank[S];
__device__ int      g_wcount[NCHUNK * E];
__device__ int      g_base[NCHUNK * E];
__device__ int      g_wtot[E];
__device__ float    g_laux;
__device__ unsigned g_ticket;
__device__ unsigned g_zdone;     // zero blocks completed
__device__ unsigned g_bdone;     // base_kernel blocks completed (branch B)

__device__ __forceinline__ u64 pack2(float x) {
    u64 r;
    asm("mov.b64 %0, {%1, %1};" : "=l"(r) : "f"(x));
    return r;
}
__device__ __forceinline__ void ffma2(u64 &d, u64 a, u64 b) {
    asm("fma.rn.f32x2 %0, %1, %2, %0;" : "+l"(d) : "l"(a), "l"(b));
}

// ---------------------------------------------------------------------------
// Branch A: persistent zeroing kernel + fused scatter tail.
// Release-acquire: every block fences once after its tiles, increments
// g_zdone; the last block acquires all zero stores, waits for branch B's
// release counter (never actually spins: branch B ends ~65us, wall ~150us),
// scatters the <=2*S nonzeros, writes scalars, resets counters.
// ---------------------------------------------------------------------------
__global__ void __launch_bounds__(256, 2)
zero_scatter_kernel(float* __restrict__ out, size_t out_elems,
                    size_t SEC, int CAPV) {
    const int tid = threadIdx.x;
    const int lane = tid & 31;
    const size_t total4 = out_elems >> 2;

    if (blockIdx.x == 0 && tid == 0) {   // tail elements (out_elems % 4)
        for (size_t r = total4 * 4; r < out_elems; ++r)
            out[r] = 0.f;
    }

    // ---- work-stolen zeroing ----
    float4* o4 = (float4*)out;
    const float4 z = make_float4(0.f, 0.f, 0.f, 0.f);
    for (;;) {
        unsigned t = 0;
        if (lane == 0) t = atomicAdd(&g_ticket, 1u);
        t = __shfl_sync(0xffffffffu, t, 0);
        size_t b = (size_t)t * TILE4;
        if (b >= total4) break;
        if (b + TILE4 <= total4) {
#pragma unroll 8
            for (int j = lane; j < TILE4; j += 32)
                __stcs(o4 + b + j, z);
        } else {
            for (size_t j = b + lane; j < total4; j += 32)
                __stcs(o4 + j, z);
        }
    }

    // ---- completion arbitration ----
    __syncthreads();
    __threadfence();                       // release this block's zero stores
    __shared__ unsigned s_old;
    if (tid == 0) s_old = atomicAdd(&g_zdone, 1u);
    __syncthreads();
    if (s_old != NZERO - 1) return;

    // Last block: acquire all zero stores; wait for branch B completion.
    if (tid == 0) {
        while (atomicAdd(&g_bdone, 0u) < E) { }   // branch B release counter
    }
    __syncthreads();
    __threadfence();                       // acquire branch B's results

    // ---- scatter the nonzeros ----
    for (int s = tid; s < S; s += 256) {
        const int e = g_expert[s];
        const int pos = g_base[(s >> 5) * E + e] + g_rank[s];
        if (pos < CAPV) {
            size_t o = 1 + ((size_t)s * E + e) * (size_t)CAPV + pos;
            out[o]       = g_gate[s];   // combine_weights
            out[o + SEC] = 1.0f;        // dispatch_mask
        }
    }
    // scalars + counter resets for the next call/replay
    if (tid < E) out[1 + 2 * SEC + tid] = (float)g_wtot[tid];
    if (tid == 0) {
        out[0]   = g_laux;
        g_ticket = 0u;
        g_zdone  = 0u;
        g_bdone  = 0u;
    }
}

// ---------------------------------------------------------------------------
// Branch B kernel 1: zero scratch (logits accumulator, histograms, colsum).
// ---------------------------------------------------------------------------
__global__ void init_kernel() {
    int i = blockIdx.x * blockDim.x + threadIdx.x;
    float4 z = make_float4(0.f, 0.f, 0.f, 0.f);
    float4* p = (float4*)g_logits;
    const int n4 = (S * E) / 4;   // 131072
    for (int j = i; j < n4; j += gridDim.x * blockDim.x) p[j] = z;
    int4* w4 = (int4*)g_wcount;
    const int nw4 = (NCHUNK * E) / 4;  // 4096
    for (int j = i; j < nw4; j += gridDim.x * blockDim.x)
        w4[j] = make_int4(0, 0, 0, 0);
    if (i < E) g_colsum[i] = 0.f;
    if (i == 0) g_laux = 0.f;
}

// ---------------------------------------------------------------------------
// Branch B kernel 2: split-K GEMM -> atomic accumulate logits.
// ---------------------------------------------------------------------------
__global__ void __launch_bounds__(256, 2)
gemm_kernel(const float* __restrict__ in, const float* __restrict__ wgt) {
    const int tid = threadIdx.x;
    const int lane = tid & 31;
    const int warp = tid >> 5;

    const int cid = blockIdx.x;
    const int tb  = cid & (S / TOKB - 1);   // token block 0..31
    const int ks  = cid / (S / TOKB);       // k-split 0..3
    const int s0  = tb * TOKB;
    const int k0  = ks * KSLICE;

    __shared__ float As[KC][TOKB + 1];
    __shared__ float Bs[KC][E];

    const int myTok = s0 + warp * 32 + lane;

    u64 acc[E / 2];
#pragma unroll
    for (int j = 0; j < E / 2; ++j) acc[j] = 0ull;

    const int a_tok = tid >> 3;
    const int a_kq  = tid & 7;

    for (int c = 0; c < KSLICE / KC; ++c) {
        const int kc = k0 + c * KC;
#pragma unroll
        for (int p = 0; p < 8; ++p) {
            int t = p * 32 + a_tok;
            float4 v = *(const float4*)(in + (size_t)(s0 + t) * M + kc + a_kq * 4);
            As[a_kq * 4 + 0][t] = v.x;
            As[a_kq * 4 + 1][t] = v.y;
            As[a_kq * 4 + 2][t] = v.z;
            As[a_kq * 4 + 3][t] = v.w;
        }
#pragma unroll
        for (int r = 0; r < 2; ++r) {
            int q = tid * 2 + r;
            int e = q >> 3, kq = q & 7;
            float4 v = *(const float4*)(wgt + (size_t)e * M + kc + kq * 4);
            Bs[kq * 4 + 0][e] = v.x;
            Bs[kq * 4 + 1][e] = v.y;
            Bs[kq * 4 + 2][e] = v.z;
            Bs[kq * 4 + 3][e] = v.w;
        }
        __syncthreads();
#pragma unroll
        for (int kk = 0; kk < KC; ++kk) {
            float a = As[kk][tid & 255];
            u64 aa = pack2(a);
            const ulonglong2* b2 = (const ulonglong2*)(&Bs[kk][0]);
#pragma unroll
            for (int j = 0; j < 16; ++j) {
                ulonglong2 bv = b2[j];
                ffma2(acc[2 * j + 0], aa, bv.x);
                ffma2(acc[2 * j + 1], aa, bv.y);
            }
        }
        __syncthreads();
    }

    float* lrow = g_logits + (size_t)myTok * E;
#pragma unroll
    for (int j = 0; j < E / 2; ++j) {
        float2 v = *(float2*)&acc[j];
        atomicAdd(lrow + 2 * j + 0, v.x);
        atomicAdd(lrow + 2 * j + 1, v.y);
    }
}

// ---------------------------------------------------------------------------
// Branch B kernel 3: softmax + argmax + per-chunk ranks/histograms + colsum.
// ---------------------------------------------------------------------------
__global__ void softmax_kernel() {
    const int tid = threadIdx.x;
    const int s   = blockIdx.x * 256 + tid;
    const int lane = tid & 31;

    float x[E];
    float4* row = (float4*)(g_logits + (size_t)s * E);
#pragma unroll
    for (int j = 0; j < E / 4; ++j) {
        float4 v = row[j];
        x[4 * j + 0] = v.x; x[4 * j + 1] = v.y;
        x[4 * j + 2] = v.z; x[4 * j + 3] = v.w;
    }
    float mx = x[0];
    int am = 0;
#pragma unroll
    for (int j = 1; j < E; ++j) {
        if (x[j] > mx) { mx = x[j]; am = j; }   // strict > keeps first max
    }
    float sum = 0.f;
#pragma unroll
    for (int j = 0; j < E; ++j) sum += __expf(x[j] - mx);
    float inv = 1.f / sum;

    g_expert[s] = am;
    g_gate[s]   = inv;          // gate at argmax = exp(0)/sum

    unsigned grp = __match_any_sync(0xffffffffu, am);
    int rank = __popc(grp & ((1u << lane) - 1u));
    g_rank[s] = rank;
    if (rank == 0) g_wcount[(s >> 5) * E + am] = __popc(grp);

    // Overwrite logits row with normalized gates
#pragma unroll
    for (int j = 0; j < E / 4; ++j) {
        float4 v;
        v.x = __expf(x[4 * j + 0] - mx) * inv;
        v.y = __expf(x[4 * j + 1] - mx) * inv;
        v.z = __expf(x[4 * j + 2] - mx) * inv;
        v.w = __expf(x[4 * j + 3] - mx) * inv;
        row[j] = v;
    }
    __syncthreads();

    // Column sums of gates (for l_aux), this block's tokens only
    const int e    = tid & 63;
    const int grp2 = tid >> 6;
    const int base = blockIdx.x * 256 + grp2 * 64;
    float part = 0.f;
#pragma unroll 4
    for (int i = 0; i < 64; ++i)
        part += g_logits[(size_t)(base + i) * E + e];
    atomicAdd(&g_colsum[e], part);
}

// ---------------------------------------------------------------------------
// Branch B kernel 4: per-expert exclusive prefix over 256 chunk counts.
// Results to scratch; releases via g_bdone (one increment per block).
// ---------------------------------------------------------------------------
__global__ void base_kernel() {
    const int e = blockIdx.x;
    const int c = threadIdx.x;          // chunk 0..255
    const int lane = c & 31, w = c >> 5;

    int v = g_wcount[c * E + e];
    int x = v;
#pragma unroll
    for (int d = 1; d < 32; d <<= 1) {
        int t = __shfl_up_sync(0xffffffffu, x, d);
        if (lane >= d) x += t;
    }
    __shared__ int wsum[8];
    if (lane == 31) wsum[w] = x;
    __syncthreads();
    if (c == 0) {
        int a = 0;
#pragma unroll
        for (int i = 0; i < 8; ++i) { int t = wsum[i]; wsum[i] = a; a += t; }
    }
    __syncthreads();
    int excl = x - v + wsum[w];
    g_base[c * E + e] = excl;

    if (c == 255) {
        int tot = excl + v;
        g_wtot[e] = tot;
        float term = g_colsum[e] * (float)tot *
                     ((float)E / ((float)S * (float)S));
        atomicAdd(&g_laux, term);
    }
    // release: all of this block's results visible before counting it done
    __syncthreads();
    __threadfence();
    if (c == 0) atomicAdd(&g_bdone, 1u);
}

// ---------------------------------------------------------------------------
// Stream/event objects: created once at program start (static constructor),
// outside graph capture. No device memory involved.
// ---------------------------------------------------------------------------
static cudaStream_t s_branchB;
static cudaEvent_t  s_evFork;
static cudaEvent_t  s_evJoin;
namespace {
struct StreamInit {
    StreamInit() {
        cudaStreamCreateWithFlags(&s_branchB, cudaStreamNonBlocking);
        cudaEventCreateWithFlags(&s_evFork, cudaEventDisableTiming);
        cudaEventCreateWithFlags(&s_evJoin, cudaEventDisableTiming);
    }
};
static StreamInit s_streamInit;
}

// ---------------------------------------------------------------------------
extern "C" void kernel_launch(void* const* d_in, const int* in_sizes, int n_in,
                              void* d_out, int out_size) {
    const float* in  = (const float*)d_in[0];
    const float* wgt = (const float*)d_in[1];
    float* out = (float*)d_out;

    // Derive capacity from out_size; fall back to the analytic value (128).
    long long c = ((long long)out_size - 1 - E) / (2LL * S * E);
    int CAPV = 128;
    if (c > 0 && (1 + 2LL * S * E * c + E) == (long long)out_size)
        CAPV = (int)c;
    size_t SEC = (size_t)S * E * (size_t)CAPV;

    // Fork branch B (routing pipeline) so it runs under the zeroing wall.
    cudaEventRecord(s_evFork, 0);
    cudaStreamWaitEvent(s_branchB, s_evFork, 0);

    init_kernel<<<128, 256, 0, s_branchB>>>();
    gemm_kernel<<<NCOMPUTE, 256, 0, s_branchB>>>(in, wgt);
    softmax_kernel<<<S / 256, 256, 0, s_branchB>>>();
    base_kernel<<<E, 256, 0, s_branchB>>>();
    cudaEventRecord(s_evJoin, s_branchB);

    // Branch A: the 537 MB zeroing wall with fused scatter tail.
    zero_scatter_kernel<<<NZERO, 256>>>(out, (size_t)out_size, SEC, CAPV);

    // Join branch B back into the capture stream (graph completeness).
    cudaStreamWaitEvent(0, s_evJoin, 0);
}

// round 13
// speedup vs baseline: 1.2259x; 1.2259x over previous
#include <cuda_runtime.h>
#include <cstdint>
#include <cstddef>

// Problem shape (fixed by the dataset)
#define S 8192
#define M 2048
#define E 64

#define KSPLIT 4
#define KSLICE (M / KSPLIT)      // 512
#define KC 32
#define TOKB 256                 // tokens per compute block
#define NCOMPUTE ((S / TOKB) * KSPLIT)   // 128
#define NCHUNK (S / 32)          // 256 warp-sized token chunks

typedef unsigned long long u64;

// Scratch (device globals — no allocations allowed)
__device__ float    g_logits[(size_t)S * E];   // 2 MB split-K accumulator
__device__ float    g_colsum[E];
__device__ int      g_expert[S];
__device__ float    g_gate[S];
__device__ int      g_rank[S];
__device__ int      g_wcount[NCHUNK * E];
__device__ int      g_base[NCHUNK * E];
__device__ int      g_wtot[E];
__device__ float    g_laux;

__device__ __forceinline__ u64 pack2(float x) {
    u64 r;
    asm("mov.b64 %0, {%1, %1};" : "=l"(r) : "f"(x));
    return r;
}
__device__ __forceinline__ void ffma2(u64 &d, u64 a, u64 b) {
    asm("fma.rn.f32x2 %0, %1, %2, %0;" : "+l"(d) : "l"(a), "l"(b));
}

// ---------------------------------------------------------------------------
// Branch B kernel 1: zero scratch (logits accumulator, histograms, colsum).
// ---------------------------------------------------------------------------
__global__ void init_kernel() {
    int i = blockIdx.x * blockDim.x + threadIdx.x;
    float4 z = make_float4(0.f, 0.f, 0.f, 0.f);
    float4* p = (float4*)g_logits;
    const int n4 = (S * E) / 4;   // 131072
    for (int j = i; j < n4; j += gridDim.x * blockDim.x) p[j] = z;
    int4* w4 = (int4*)g_wcount;
    const int nw4 = (NCHUNK * E) / 4;  // 4096
    for (int j = i; j < nw4; j += gridDim.x * blockDim.x)
        w4[j] = make_int4(0, 0, 0, 0);
    if (i < E) g_colsum[i] = 0.f;
    if (i == 0) g_laux = 0.f;
}

// ---------------------------------------------------------------------------
// Branch B kernel 2: split-K GEMM -> atomic accumulate logits.
// ---------------------------------------------------------------------------
__global__ void __launch_bounds__(256, 2)
gemm_kernel(const float* __restrict__ in, const float* __restrict__ wgt) {
    const int tid = threadIdx.x;
    const int lane = tid & 31;
    const int warp = tid >> 5;

    const int cid = blockIdx.x;
    const int tb  = cid & (S / TOKB - 1);   // token block 0..31
    const int ks  = cid / (S / TOKB);       // k-split 0..3
    const int s0  = tb * TOKB;
    const int k0  = ks * KSLICE;

    __shared__ float As[KC][TOKB + 1];
    __shared__ float Bs[KC][E];

    const int myTok = s0 + warp * 32 + lane;

    u64 acc[E / 2];
#pragma unroll
    for (int j = 0; j < E / 2; ++j) acc[j] = 0ull;

    const int a_tok = tid >> 3;
    const int a_kq  = tid & 7;

    for (int c = 0; c < KSLICE / KC; ++c) {
        const int kc = k0 + c * KC;
#pragma unroll
        for (int p = 0; p < 8; ++p) {
            int t = p * 32 + a_tok;
            float4 v = *(const float4*)(in + (size_t)(s0 + t) * M + kc + a_kq * 4);
            As[a_kq * 4 + 0][t] = v.x;
            As[a_kq * 4 + 1][t] = v.y;
            As[a_kq * 4 + 2][t] = v.z;
            As[a_kq * 4 + 3][t] = v.w;
        }
#pragma unroll
        for (int r = 0; r < 2; ++r) {
            int q = tid * 2 + r;
            int e = q >> 3, kq = q & 7;
            float4 v = *(const float4*)(wgt + (size_t)e * M + kc + kq * 4);
            Bs[kq * 4 + 0][e] = v.x;
            Bs[kq * 4 + 1][e] = v.y;
            Bs[kq * 4 + 2][e] = v.z;
            Bs[kq * 4 + 3][e] = v.w;
        }
        __syncthreads();
#pragma unroll
        for (int kk = 0; kk < KC; ++kk) {
            float a = As[kk][tid & 255];
            u64 aa = pack2(a);
            const ulonglong2* b2 = (const ulonglong2*)(&Bs[kk][0]);
#pragma unroll
            for (int j = 0; j < 16; ++j) {
                ulonglong2 bv = b2[j];
                ffma2(acc[2 * j + 0], aa, bv.x);
                ffma2(acc[2 * j + 1], aa, bv.y);
            }
        }
        __syncthreads();
    }

    float* lrow = g_logits + (size_t)myTok * E;
#pragma unroll
    for (int j = 0; j < E / 2; ++j) {
        float2 v = *(float2*)&acc[j];
        atomicAdd(lrow + 2 * j + 0, v.x);
        atomicAdd(lrow + 2 * j + 1, v.y);
    }
}

// ---------------------------------------------------------------------------
// Branch B kernel 3: softmax + argmax + per-chunk ranks/histograms + colsum.
// ---------------------------------------------------------------------------
__global__ void softmax_kernel() {
    const int tid = threadIdx.x;
    const int s   = blockIdx.x * 256 + tid;
    const int lane = tid & 31;

    float x[E];
    float4* row = (float4*)(g_logits + (size_t)s * E);
#pragma unroll
    for (int j = 0; j < E / 4; ++j) {
        float4 v = row[j];
        x[4 * j + 0] = v.x; x[4 * j + 1] = v.y;
        x[4 * j + 2] = v.z; x[4 * j + 3] = v.w;
    }
    float mx = x[0];
    int am = 0;
#pragma unroll
    for (int j = 1; j < E; ++j) {
        if (x[j] > mx) { mx = x[j]; am = j; }   // strict > keeps first max
    }
    float sum = 0.f;
#pragma unroll
    for (int j = 0; j < E; ++j) sum += __expf(x[j] - mx);
    float inv = 1.f / sum;

    g_expert[s] = am;
    g_gate[s]   = inv;          // gate at argmax = exp(0)/sum

    unsigned grp = __match_any_sync(0xffffffffu, am);
    int rank = __popc(grp & ((1u << lane) - 1u));
    g_rank[s] = rank;
    if (rank == 0) g_wcount[(s >> 5) * E + am] = __popc(grp);

    // Overwrite logits row with normalized gates
#pragma unroll
    for (int j = 0; j < E / 4; ++j) {
        float4 v;
        v.x = __expf(x[4 * j + 0] - mx) * inv;
        v.y = __expf(x[4 * j + 1] - mx) * inv;
        v.z = __expf(x[4 * j + 2] - mx) * inv;
        v.w = __expf(x[4 * j + 3] - mx) * inv;
        row[j] = v;
    }
    __syncthreads();

    // Column sums of gates (for l_aux), this block's tokens only
    const int e    = tid & 63;
    const int grp2 = tid >> 6;
    const int base = blockIdx.x * 256 + grp2 * 64;
    float part = 0.f;
#pragma unroll 4
    for (int i = 0; i < 64; ++i)
        part += g_logits[(size_t)(base + i) * E + e];
    atomicAdd(&g_colsum[e], part);
}

// ---------------------------------------------------------------------------
// Branch B kernel 4: per-expert exclusive prefix over 256 chunk counts.
// Results to scratch (out may still be mid-memset).
// ---------------------------------------------------------------------------
__global__ void base_kernel() {
    const int e = blockIdx.x;
    const int c = threadIdx.x;          // chunk 0..255
    const int lane = c & 31, w = c >> 5;

    int v = g_wcount[c * E + e];
    int x = v;
#pragma unroll
    for (int d = 1; d < 32; d <<= 1) {
        int t = __shfl_up_sync(0xffffffffu, x, d);
        if (lane >= d) x += t;
    }
    __shared__ int wsum[8];
    if (lane == 31) wsum[w] = x;
    __syncthreads();
    if (c == 0) {
        int a = 0;
#pragma unroll
        for (int i = 0; i < 8; ++i) { int t = wsum[i]; wsum[i] = a; a += t; }
    }
    __syncthreads();
    int excl = x - v + wsum[w];
    g_base[c * E + e] = excl;

    if (c == 255) {
        int tot = excl + v;
        g_wtot[e] = tot;
        float term = g_colsum[e] * (float)tot *
                     ((float)E / ((float)S * (float)S));
        atomicAdd(&g_laux, term);
    }
}

// ---------------------------------------------------------------------------
// Join kernel: scatter nonzeros into the zeroed output + scalars.
// ---------------------------------------------------------------------------
__global__ void scatter_kernel(float* __restrict__ out, size_t SEC, int CAPV) {
    const int s = blockIdx.x * 256 + threadIdx.x;
    const int e = g_expert[s];
    const int pos = g_base[(s >> 5) * E + e] + g_rank[s];
    if (pos < CAPV) {
        size_t o = 1 + ((size_t)s * E + e) * (size_t)CAPV + pos;
        out[o]       = g_gate[s];   // combine_weights
        out[o + SEC] = 1.0f;        // dispatch_mask
    }
    if (blockIdx.x == 0) {
        const int tid = threadIdx.x;
        if (tid < E) out[1 + 2 * SEC + tid] = (float)g_wtot[tid];
        if (tid == 0) out[0] = g_laux;
    }
}

// ---------------------------------------------------------------------------
// Stream/event objects: created once at program start (static constructor),
// outside graph capture. No device memory involved.
// ---------------------------------------------------------------------------
static cudaStream_t s_branchB;
static cudaEvent_t  s_evFork;
static cudaEvent_t  s_evJoin;
namespace {
struct StreamInit {
    StreamInit() {
        cudaStreamCreateWithFlags(&s_branchB, cudaStreamNonBlocking);
        cudaEventCreateWithFlags(&s_evFork, cudaEventDisableTiming);
        cudaEventCreateWithFlags(&s_evJoin, cudaEventDisableTiming);
    }
};
static StreamInit s_streamInit;
}

// ---------------------------------------------------------------------------
extern "C" void kernel_launch(void* const* d_in, const int* in_sizes, int n_in,
                              void* d_out, int out_size) {
    const float* in  = (const float*)d_in[0];
    const float* wgt = (const float*)d_in[1];
    float* out = (float*)d_out;

    // Derive capacity from out_size; fall back to the analytic value (128).
    long long c = ((long long)out_size - 1 - E) / (2LL * S * E);
    int CAPV = 128;
    if (c > 0 && (1 + 2LL * S * E * c + E) == (long long)out_size)
        CAPV = (int)c;
    size_t SEC = (size_t)S * E * (size_t)CAPV;

    // Fork branch B (routing pipeline); it runs under the memset wall and
    // uses SM resources the memset doesn't need.
    cudaEventRecord(s_evFork, 0);
    cudaStreamWaitEvent(s_branchB, s_evFork, 0);

    init_kernel<<<128, 256, 0, s_branchB>>>();
    gemm_kernel<<<NCOMPUTE, 256, 0, s_branchB>>>(in, wgt);
    softmax_kernel<<<S / 256, 256, 0, s_branchB>>>();
    base_kernel<<<E, 256, 0, s_branchB>>>();
    cudaEventRecord(s_evJoin, s_branchB);

    // Branch A: driver-optimized zeroing of the whole output (graph memset
    // node — capture-legal, allocation-free).
    cudaMemsetAsync(out, 0, (size_t)out_size * sizeof(float), 0);

    // Join + scatter
    cudaStreamWaitEvent(0, s_evJoin, 0);
    scatter_kernel<<<S / 256, 256>>>(out, SEC, CAPV);
}